// round 11
// baseline (speedup 1.0000x reference)
#include <cuda_runtime.h>
#include <math.h>

#define BB 256
#define IN_DIM 1152

// packed f32x2 helpers (Blackwell sm_103a)
#define PACK_F32X2(out, lo, hi) \
    asm("mov.b64 %0, {%1, %2};" : "=l"(out) : "f"(lo), "f"(hi))
#define UNPACK_F32X2(lo, hi, in) \
    asm("mov.b64 {%0, %1}, %2;" : "=f"(lo), "=f"(hi) : "l"(in))
#define FFMA2(acc, a, b) \
    asm("fma.rn.f32x2 %0, %1, %2, %0;" : "+l"(acc) : "l"(a), "l"(b))

// ---- scratch (static device globals; no allocations anywhere) ----
__device__ float g_h[(size_t)BB * 256 * 400];        // conv1 out [B,256,20,20]
__device__ float g_pc[(size_t)BB * 256 * 36];        // primary conv out [B,256,6,6]
__device__ float g_x3[(size_t)BB * IN_DIM * 8];      // squashed+transposed [B,1152,8]
__device__ float g_votes[(size_t)BB * IN_DIM * 160]; // [B,1152,10,16]
__device__ float g_logits[(size_t)BB * IN_DIM * 10]; // [B,1152,10]
__device__ float g_r1[BB * 512];
__device__ float g_r2[BB * 1024];

// ---------------- conv1: [B,1,28,28] -> relu([B,256,20,20]) ----------------
__global__ void conv1_kernel(const float* __restrict__ x,
                             const float* __restrict__ w,
                             const float* __restrict__ bias) {
    int oc = blockIdx.x, b = blockIdx.y;
    int tid = threadIdx.x; // 400 threads = 20x20
    __shared__ float s_img[784];
    __shared__ float s_w[81];
    for (int idx = tid; idx < 784; idx += 400) s_img[idx] = x[b * 784 + idx];
    if (tid < 81) s_w[tid] = w[oc * 81 + tid];
    __syncthreads();
    int oy = tid / 20, ox = tid % 20;
    float acc = bias[oc];
#pragma unroll
    for (int kh = 0; kh < 9; kh++)
#pragma unroll
        for (int kw = 0; kw < 9; kw++)
            acc += s_img[(oy + kh) * 28 + ox + kw] * s_w[kh * 9 + kw];
    g_h[((size_t)(b * 256 + oc)) * 400 + tid] = fmaxf(acc, 0.f);
}

// ------- primary caps conv: [B,256,20,20] -> [B,256,6,6], k=9 s=2 -------
// block = (oc tile of 64, image pair b0..b0+1); 144 threads;
// each thread: 2 images x 4 oc x 4 pos, images packed in f32x2.
__global__ void pconv_kernel(const float* __restrict__ w) {
    int oc0 = blockIdx.x * 64;
    int b0 = blockIdx.y * 2;
    int tid = threadIdx.x; // 144
    int ocg = tid & 15;    // 16 groups of 4 oc
    int posg = tid >> 4;   // 9 groups of 4 positions
    __shared__ float s_h[2][361];    // 19x19 input patch, one ic, 2 images
    __shared__ float s_w[64 * 81];   // 64 oc x 9x9, one ic
    unsigned long long acc2[4][4];   // [oc][pos], lanes = (img0, img1)
#pragma unroll
    for (int j = 0; j < 4; j++)
#pragma unroll
        for (int p = 0; p < 4; p++) acc2[j][p] = 0ull;
    int prow[4], pcol[4];
#pragma unroll
    for (int p = 0; p < 4; p++) {
        int pos = posg * 4 + p;
        prow[p] = (pos / 6) * 2;
        pcol[p] = (pos % 6) * 2;
    }
    for (int ic = 0; ic < 256; ic++) {
        const float* hp0 = g_h + ((size_t)(b0 * 256 + ic)) * 400;
        const float* hp1 = g_h + ((size_t)((b0 + 1) * 256 + ic)) * 400;
        for (int idx = tid; idx < 722; idx += 144) {
            int im = idx >= 361;
            int r = idx - im * 361;
            const float* hp = im ? hp1 : hp0;
            s_h[im][r] = hp[(r / 19) * 20 + r % 19];
        }
        for (int idx = tid; idx < 64 * 81; idx += 144) {
            int j = idx / 81, k = idx - j * 81;
            s_w[idx] = w[((size_t)(oc0 + j) * 256 + ic) * 81 + k];
        }
        __syncthreads();
#pragma unroll
        for (int kh = 0; kh < 9; kh++) {
#pragma unroll
            for (int kw = 0; kw < 9; kw++) {
                unsigned long long hv2[4];
#pragma unroll
                for (int p = 0; p < 4; p++) {
                    int off = (prow[p] + kh) * 19 + pcol[p] + kw;
                    float h0 = s_h[0][off];
                    float h1 = s_h[1][off];
                    PACK_F32X2(hv2[p], h0, h1);
                }
                unsigned long long wv2[4];
#pragma unroll
                for (int j = 0; j < 4; j++) {
                    float wv = s_w[(ocg * 4 + j) * 81 + kh * 9 + kw];
                    PACK_F32X2(wv2[j], wv, wv);
                }
#pragma unroll
                for (int j = 0; j < 4; j++)
#pragma unroll
                    for (int p = 0; p < 4; p++)
                        FFMA2(acc2[j][p], wv2[j], hv2[p]);
            }
        }
        __syncthreads();
    }
#pragma unroll
    for (int j = 0; j < 4; j++) {
        int oc = oc0 + ocg * 4 + j;
#pragma unroll
        for (int p = 0; p < 4; p++) {
            int pos = posg * 4 + p;
            float a0, a1;
            UNPACK_F32X2(a0, a1, acc2[j][p]);
            g_pc[((size_t)(b0 * 256 + oc)) * 36 + pos] = a0;
            g_pc[((size_t)((b0 + 1) * 256 + oc)) * 36 + pos] = a1;
        }
    }
}

// ---- primary squash + transpose -> x3 [B,1152,8] ----
__global__ void squash_prim_kernel(const float* __restrict__ prim_b) {
    int g = blockIdx.x * blockDim.x + threadIdx.x;
    if (g >= BB * IN_DIM) return;
    int i = g % IN_DIM;
    int b = g / IN_DIM;
    int cap = i / 36, pos = i % 36;
    float s[8];
    float n2 = 0.f;
#pragma unroll
    for (int a = 0; a < 8; a++) {
        float v = g_pc[((size_t)(b * 256 + cap * 8 + a)) * 36 + pos] * (1.f / 32.f)
                  + prim_b[cap * 8 + a];
        s[a] = v;
        n2 += v * v;
    }
    float scale = (n2 / (1.f + n2)) * rsqrtf(n2 + 1e-9f);
#pragma unroll
    for (int a = 0; a < 8; a++) g_x3[(size_t)g * 8 + a] = s[a] * scale;
}

// ---- votes[b,i,o,t] = sum_a x3[b,i,a] * W[i,a,o,t]; block = i, W stays in smem ----
__global__ void votes_kernel(const float* __restrict__ dw) {
    int i = blockIdx.x;
    int t = threadIdx.x; // 160
    __shared__ float s_w[1280];
    for (int idx = t; idx < 1280; idx += 160) s_w[idx] = dw[(size_t)i * 1280 + idx];
    __syncthreads();
    for (int b = 0; b < BB; b++) {
        const float* xp = g_x3 + ((size_t)b * IN_DIM + i) * 8;
        float acc = 0.f;
#pragma unroll
        for (int a = 0; a < 8; a++) acc += xp[a] * s_w[a * 160 + t];
        g_votes[((size_t)b * IN_DIM + i) * 160 + t] = acc;
    }
}

// ---- one full routing iteration per launch: softmax -> preact -> squash -> logit update ----
__global__ void routing_kernel(const float* __restrict__ db,
                               float* __restrict__ out_digit,
                               int iter, int last) {
    int b = blockIdx.x;
    int tid = threadIdx.x; // 320
    __shared__ float s_route[IN_DIM * 10]; // 46080 B
    __shared__ float s_part[2 * 160];
    __shared__ float s_act[160];
    __shared__ float s_scale[10];
    const float* vbase = g_votes + (size_t)b * IN_DIM * 160;
    float* lbase = g_logits + (size_t)b * IN_DIM * 10;

    if (iter == 0) {
        for (int idx = tid; idx < IN_DIM * 10; idx += 320) s_route[idx] = 0.1f;
    } else {
        for (int i = tid; i < IN_DIM; i += 320) {
            float l[10];
            float m = -1e30f;
#pragma unroll
            for (int o = 0; o < 10; o++) { l[o] = lbase[i * 10 + o]; m = fmaxf(m, l[o]); }
            float s = 0.f;
#pragma unroll
            for (int o = 0; o < 10; o++) { l[o] = expf(l[o] - m); s += l[o]; }
            float inv = 1.f / s;
#pragma unroll
            for (int o = 0; o < 10; o++) s_route[i * 10 + o] = l[o] * inv;
        }
    }
    __syncthreads();

    // preact[b,o,t] = sum_i route * votes (i-range split 2 ways)
    {
        int g = tid / 160, ot = tid % 160, o = ot >> 4;
        float acc = 0.f;
        int i0 = g * 576, i1 = i0 + 576;
#pragma unroll 4
        for (int i = i0; i < i1; i++)
            acc += s_route[i * 10 + o] * vbase[(size_t)i * 160 + ot];
        s_part[g * 160 + ot] = acc;
    }
    __syncthreads();
    if (tid < 160) s_part[tid] = s_part[tid] + s_part[160 + tid] + db[tid];
    __syncthreads();
    if (tid < 10) {
        float n2 = 0.f;
#pragma unroll
        for (int t = 0; t < 16; t++) { float v = s_part[tid * 16 + t]; n2 += v * v; }
        s_scale[tid] = (n2 / (1.f + n2)) * rsqrtf(n2 + 1e-9f);
    }
    __syncthreads();
    if (tid < 160) {
        float a = s_part[tid] * s_scale[tid >> 4];
        s_act[tid] = a;
        if (last) out_digit[b * 160 + tid] = a;
    }
    if (!last) {
        __syncthreads();
        for (int idx = tid; idx < IN_DIM * 10; idx += 320) {
            int i = idx / 10, o = idx - i * 10;
            const float* vp = vbase + (size_t)i * 160 + o * 16;
            float s = 0.f;
#pragma unroll
            for (int t = 0; t < 16; t++) s += vp[t] * s_act[o * 16 + t];
            if (iter == 0) lbase[idx] = s;
            else lbase[idx] += s;
        }
    }
}

// ---- reconstruction MLP (A-stationary in smem, coalesced weight reads, 4 batches/block) ----
__global__ void fc1_kernel(const float* __restrict__ yv, const float* __restrict__ w1,
                           const float* __restrict__ b1, const float* __restrict__ digit) {
    int b0 = blockIdx.x * 4;
    int j = threadIdx.x; // 512
    __shared__ float s_in[4][160];
    for (int idx = j; idx < 640; idx += 512) {
        int g = idx / 160, ot = idx - g * 160;
        s_in[g][ot] = digit[(b0 + g) * 160 + ot] * yv[(b0 + g) * 10 + (ot >> 4)];
    }
    __syncthreads();
    float a0 = b1[j], a1 = a0, a2 = a0, a3 = a0;
#pragma unroll 4
    for (int k = 0; k < 160; k++) {
        float wv = w1[k * 512 + j];
        a0 += s_in[0][k] * wv; a1 += s_in[1][k] * wv;
        a2 += s_in[2][k] * wv; a3 += s_in[3][k] * wv;
    }
    g_r1[(b0 + 0) * 512 + j] = fmaxf(a0, 0.f);
    g_r1[(b0 + 1) * 512 + j] = fmaxf(a1, 0.f);
    g_r1[(b0 + 2) * 512 + j] = fmaxf(a2, 0.f);
    g_r1[(b0 + 3) * 512 + j] = fmaxf(a3, 0.f);
}

__global__ void fc2_kernel(const float* __restrict__ w2, const float* __restrict__ b2) {
    int b0 = blockIdx.x * 4;
    int j = threadIdx.x; // 1024
    __shared__ float s_in[4][512];
    for (int idx = j; idx < 2048; idx += 1024) {
        int g = idx >> 9, k = idx & 511;
        s_in[g][k] = g_r1[(b0 + g) * 512 + k];
    }
    __syncthreads();
    float a0 = b2[j], a1 = a0, a2 = a0, a3 = a0;
#pragma unroll 4
    for (int k = 0; k < 512; k++) {
        float wv = w2[k * 1024 + j];
        a0 += s_in[0][k] * wv; a1 += s_in[1][k] * wv;
        a2 += s_in[2][k] * wv; a3 += s_in[3][k] * wv;
    }
    g_r2[(b0 + 0) * 1024 + j] = fmaxf(a0, 0.f);
    g_r2[(b0 + 1) * 1024 + j] = fmaxf(a1, 0.f);
    g_r2[(b0 + 2) * 1024 + j] = fmaxf(a2, 0.f);
    g_r2[(b0 + 3) * 1024 + j] = fmaxf(a3, 0.f);
}

__global__ void fc3_kernel(const float* __restrict__ w3, const float* __restrict__ b3,
                           float* __restrict__ recon) {
    int b0 = blockIdx.x * 4;
    int j = threadIdx.x; // 784
    __shared__ float s_in[4][1024];
    for (int idx = j; idx < 4096; idx += 784) {
        int g = idx >> 10, k = idx & 1023;
        s_in[g][k] = g_r2[(b0 + g) * 1024 + k];
    }
    __syncthreads();
    float a0 = b3[j], a1 = a0, a2 = a0, a3 = a0;
#pragma unroll 4
    for (int k = 0; k < 1024; k++) {
        float wv = w3[k * 784 + j];
        a0 += s_in[0][k] * wv; a1 += s_in[1][k] * wv;
        a2 += s_in[2][k] * wv; a3 += s_in[3][k] * wv;
    }
    recon[(b0 + 0) * 784 + j] = 1.f / (1.f + expf(-a0));
    recon[(b0 + 1) * 784 + j] = 1.f / (1.f + expf(-a1));
    recon[(b0 + 2) * 784 + j] = 1.f / (1.f + expf(-a2));
    recon[(b0 + 3) * 784 + j] = 1.f / (1.f + expf(-a3));
}

extern "C" void kernel_launch(void* const* d_in, const int* in_sizes, int n_in,
                              void* d_out, int out_size) {
    const float* x       = (const float*)d_in[0];
    const float* y       = (const float*)d_in[1];
    const float* conv1_w = (const float*)d_in[2];
    const float* conv1_b = (const float*)d_in[3];
    const float* prim_w  = (const float*)d_in[4];
    const float* prim_b  = (const float*)d_in[5];
    const float* digit_w = (const float*)d_in[6];
    const float* digit_b = (const float*)d_in[7];
    const float* w1      = (const float*)d_in[8];
    const float* b1      = (const float*)d_in[9];
    const float* w2      = (const float*)d_in[10];
    const float* b2      = (const float*)d_in[11];
    const float* w3      = (const float*)d_in[12];
    const float* b3      = (const float*)d_in[13];
    float* out = (float*)d_out;

    conv1_kernel<<<dim3(256, 256), 400>>>(x, conv1_w, conv1_b);
    pconv_kernel<<<dim3(4, 128), 144>>>(prim_w);
    squash_prim_kernel<<<(BB * IN_DIM + 255) / 256, 256>>>(prim_b);
    votes_kernel<<<IN_DIM, 160>>>(digit_w);
    routing_kernel<<<BB, 320>>>(digit_b, out, 0, 0);
    routing_kernel<<<BB, 320>>>(digit_b, out, 1, 0);
    routing_kernel<<<BB, 320>>>(digit_b, out, 2, 1);
    fc1_kernel<<<64, 512>>>(y, w1, b1, out);
    fc2_kernel<<<64, 1024>>>(w2, b2);
    fc3_kernel<<<64, 784>>>(w3, b3, out + 40960);
}

// round 13
// speedup vs baseline: 1.1718x; 1.1718x over previous
#include <cuda_runtime.h>
#include <math.h>

#define BB 256
#define IN_DIM 1152

// packed f32x2 helpers (Blackwell sm_103a)
#define PACK_F32X2(out, lo, hi) \
    asm("mov.b64 %0, {%1, %2};" : "=l"(out) : "f"(lo), "f"(hi))
#define UNPACK_F32X2(lo, hi, in) \
    asm("mov.b64 {%0, %1}, %2;" : "=f"(lo), "=f"(hi) : "l"(in))
#define FFMA2(acc, a, b) \
    asm("fma.rn.f32x2 %0, %1, %2, %0;" : "+l"(acc) : "l"(a), "l"(b))

// ---- scratch (static device globals; no allocations anywhere) ----
__device__ float g_h[(size_t)BB * 256 * 400];        // conv1 out [B,256,20,20]
__device__ float g_pc[(size_t)BB * 256 * 36];        // primary conv out [B,256,6,6]
__device__ float g_x3[(size_t)BB * IN_DIM * 8];      // squashed+transposed [B,1152,8]
__device__ float g_votes[(size_t)BB * IN_DIM * 160]; // [B,1152,10,16]
__device__ float g_logits[(size_t)BB * IN_DIM * 10]; // [B,1152,10]
__device__ float g_r1[BB * 512];
__device__ float g_r2[BB * 1024];

// ---------------- conv1: [B,1,28,28] -> relu([B,256,20,20]) ----------------
__global__ void conv1_kernel(const float* __restrict__ x,
                             const float* __restrict__ w,
                             const float* __restrict__ bias) {
    int oc = blockIdx.x, b = blockIdx.y;
    int tid = threadIdx.x; // 400 threads = 20x20
    __shared__ float s_img[784];
    __shared__ float s_w[81];
    for (int idx = tid; idx < 784; idx += 400) s_img[idx] = x[b * 784 + idx];
    if (tid < 81) s_w[tid] = w[oc * 81 + tid];
    __syncthreads();
    int oy = tid / 20, ox = tid % 20;
    float acc = bias[oc];
#pragma unroll
    for (int kh = 0; kh < 9; kh++)
#pragma unroll
        for (int kw = 0; kw < 9; kw++)
            acc += s_img[(oy + kh) * 28 + ox + kw] * s_w[kh * 9 + kw];
    g_h[((size_t)(b * 256 + oc)) * 400 + tid] = fmaxf(acc, 0.f);
}

// ------- primary caps conv: [B,256,20,20] -> [B,256,6,6], k=9 s=2 -------
// block = (oc tile of 64, image pair b0..b0+1); 144 threads;
// each thread: 2 images x 4 oc x 4 pos. Images interleaved in smem as
// float2 so each hv pair is a single LDS.64 (no pack needed).
__global__ void pconv_kernel(const float* __restrict__ w) {
    int oc0 = blockIdx.x * 64;
    int b0 = blockIdx.y * 2;
    int tid = threadIdx.x; // 144
    int ocg = tid & 15;    // 16 groups of 4 oc
    int posg = tid >> 4;   // 9 groups of 4 positions
    __shared__ float2 s_h2[361];     // 19x19 patch, (img0,img1) interleaved
    __shared__ float s_w[64 * 81];   // 64 oc x 9x9, one ic (j-major)
    unsigned long long acc2[4][4];   // [oc][pos], lanes = (img0, img1)
#pragma unroll
    for (int j = 0; j < 4; j++)
#pragma unroll
        for (int p = 0; p < 4; p++) acc2[j][p] = 0ull;
    int off0[4];
#pragma unroll
    for (int p = 0; p < 4; p++) {
        int pos = posg * 4 + p;
        off0[p] = (pos / 6) * 2 * 19 + (pos % 6) * 2;
    }
    for (int ic = 0; ic < 256; ic++) {
        const float* hp0 = g_h + ((size_t)(b0 * 256 + ic)) * 400;
        const float* hp1 = g_h + ((size_t)((b0 + 1) * 256 + ic)) * 400;
        for (int idx = tid; idx < 361; idx += 144) {
            int src = (idx / 19) * 20 + idx % 19;
            float2 v;
            v.x = hp0[src];
            v.y = hp1[src];
            s_h2[idx] = v;
        }
        for (int idx = tid; idx < 64 * 81; idx += 144) {
            int j = idx / 81, k = idx - j * 81;
            s_w[idx] = w[((size_t)(oc0 + j) * 256 + ic) * 81 + k];
        }
        __syncthreads();
#pragma unroll
        for (int kh = 0; kh < 9; kh++) {
#pragma unroll
            for (int kw = 0; kw < 9; kw++) {
                unsigned long long hv2[4];
#pragma unroll
                for (int p = 0; p < 4; p++)
                    hv2[p] = *reinterpret_cast<const unsigned long long*>(
                        &s_h2[off0[p] + kh * 19 + kw]);
                unsigned long long wv2[4];
#pragma unroll
                for (int j = 0; j < 4; j++) {
                    float wv = s_w[(ocg * 4 + j) * 81 + kh * 9 + kw];
                    PACK_F32X2(wv2[j], wv, wv);
                }
#pragma unroll
                for (int j = 0; j < 4; j++)
#pragma unroll
                    for (int p = 0; p < 4; p++)
                        FFMA2(acc2[j][p], wv2[j], hv2[p]);
            }
        }
        __syncthreads();
    }
#pragma unroll
    for (int j = 0; j < 4; j++) {
        int oc = oc0 + ocg * 4 + j;
#pragma unroll
        for (int p = 0; p < 4; p++) {
            int pos = posg * 4 + p;
            float a0, a1;
            UNPACK_F32X2(a0, a1, acc2[j][p]);
            g_pc[((size_t)(b0 * 256 + oc)) * 36 + pos] = a0;
            g_pc[((size_t)((b0 + 1) * 256 + oc)) * 36 + pos] = a1;
        }
    }
}

// ---- primary squash + transpose -> x3 [B,1152,8] ----
__global__ void squash_prim_kernel(const float* __restrict__ prim_b) {
    int g = blockIdx.x * blockDim.x + threadIdx.x;
    if (g >= BB * IN_DIM) return;
    int i = g % IN_DIM;
    int b = g / IN_DIM;
    int cap = i / 36, pos = i % 36;
    float s[8];
    float n2 = 0.f;
#pragma unroll
    for (int a = 0; a < 8; a++) {
        float v = g_pc[((size_t)(b * 256 + cap * 8 + a)) * 36 + pos] * (1.f / 32.f)
                  + prim_b[cap * 8 + a];
        s[a] = v;
        n2 += v * v;
    }
    float scale = (n2 / (1.f + n2)) * rsqrtf(n2 + 1e-9f);
#pragma unroll
    for (int a = 0; a < 8; a++) g_x3[(size_t)g * 8 + a] = s[a] * scale;
}

// ---- votes[b,i,o,t] = sum_a x3[b,i,a] * W[i,a,o,t] ----
// block = (i, tile of 32 b); W and x3 tile staged in smem.
__global__ void votes_kernel(const float* __restrict__ dw) {
    int i = blockIdx.x;
    int bt = blockIdx.y * 32;
    int t = threadIdx.x; // 160
    __shared__ float s_w[1280];
    __shared__ float s_x[32][8];
    for (int idx = t; idx < 1280; idx += 160) s_w[idx] = dw[(size_t)i * 1280 + idx];
    for (int idx = t; idx < 256; idx += 160) {
        int bb = idx >> 3, a = idx & 7;
        s_x[bb][a] = g_x3[((size_t)(bt + bb) * IN_DIM + i) * 8 + a];
    }
    __syncthreads();
    for (int bb = 0; bb < 32; bb++) {
        float acc = 0.f;
#pragma unroll
        for (int a = 0; a < 8; a++) acc += s_x[bb][a] * s_w[a * 160 + t];
        g_votes[((size_t)(bt + bb) * IN_DIM + i) * 160 + t] = acc;
    }
}

// ---- one full routing iteration per launch (640 threads, 4-way i-split) ----
__global__ void routing_kernel(const float* __restrict__ db,
                               float* __restrict__ out_digit,
                               int iter, int last) {
    int b = blockIdx.x;
    int tid = threadIdx.x; // 640
    __shared__ float s_route[IN_DIM * 10]; // 46080 B
    __shared__ float s_part[4 * 160];
    __shared__ float s_act[160];
    __shared__ float s_scale[10];
    const float* vbase = g_votes + (size_t)b * IN_DIM * 160;
    float* lbase = g_logits + (size_t)b * IN_DIM * 10;

    if (iter == 0) {
        for (int idx = tid; idx < IN_DIM * 10; idx += 640) s_route[idx] = 0.1f;
    } else {
        for (int i = tid; i < IN_DIM; i += 640) {
            float l[10];
            float m = -1e30f;
#pragma unroll
            for (int o = 0; o < 10; o++) { l[o] = lbase[i * 10 + o]; m = fmaxf(m, l[o]); }
            float s = 0.f;
#pragma unroll
            for (int o = 0; o < 10; o++) { l[o] = expf(l[o] - m); s += l[o]; }
            float inv = 1.f / s;
#pragma unroll
            for (int o = 0; o < 10; o++) s_route[i * 10 + o] = l[o] * inv;
        }
    }
    __syncthreads();

    // preact[b,o,t] = sum_i route * votes (i-range split 4 ways)
    {
        int g = tid / 160, ot = tid % 160, o = ot >> 4;
        float acc = 0.f;
        int i0 = g * 288, i1 = i0 + 288;
#pragma unroll 8
        for (int i = i0; i < i1; i++)
            acc += s_route[i * 10 + o] * vbase[(size_t)i * 160 + ot];
        s_part[g * 160 + ot] = acc;
    }
    __syncthreads();
    if (tid < 160)
        s_part[tid] = s_part[tid] + s_part[160 + tid] + s_part[320 + tid]
                      + s_part[480 + tid] + db[tid];
    __syncthreads();
    if (tid < 10) {
        float n2 = 0.f;
#pragma unroll
        for (int t = 0; t < 16; t++) { float v = s_part[tid * 16 + t]; n2 += v * v; }
        s_scale[tid] = (n2 / (1.f + n2)) * rsqrtf(n2 + 1e-9f);
    }
    __syncthreads();
    if (tid < 160) {
        float a = s_part[tid] * s_scale[tid >> 4];
        s_act[tid] = a;
        if (last) out_digit[b * 160 + tid] = a;
    }
    if (!last) {
        __syncthreads();
        for (int idx = tid; idx < IN_DIM * 10; idx += 640) {
            int i = idx / 10, o = idx - i * 10;
            const float* vp = vbase + (size_t)i * 160 + o * 16;
            float s = 0.f;
#pragma unroll
            for (int t = 0; t < 16; t++) s += vp[t] * s_act[o * 16 + t];
            if (iter == 0) lbase[idx] = s;
            else lbase[idx] += s;
        }
    }
}

// ---- reconstruction MLP (A-stationary in smem, coalesced weight reads, 4 batches/block) ----
__global__ void fc1_kernel(const float* __restrict__ yv, const float* __restrict__ w1,
                           const float* __restrict__ b1, const float* __restrict__ digit) {
    int b0 = blockIdx.x * 4;
    int j = threadIdx.x; // 512
    __shared__ float s_in[4][160];
    for (int idx = j; idx < 640; idx += 512) {
        int g = idx / 160, ot = idx - g * 160;
        s_in[g][ot] = digit[(b0 + g) * 160 + ot] * yv[(b0 + g) * 10 + (ot >> 4)];
    }
    __syncthreads();
    float a0 = b1[j], a1 = a0, a2 = a0, a3 = a0;
#pragma unroll 4
    for (int k = 0; k < 160; k++) {
        float wv = w1[k * 512 + j];
        a0 += s_in[0][k] * wv; a1 += s_in[1][k] * wv;
        a2 += s_in[2][k] * wv; a3 += s_in[3][k] * wv;
    }
    g_r1[(b0 + 0) * 512 + j] = fmaxf(a0, 0.f);
    g_r1[(b0 + 1) * 512 + j] = fmaxf(a1, 0.f);
    g_r1[(b0 + 2) * 512 + j] = fmaxf(a2, 0.f);
    g_r1[(b0 + 3) * 512 + j] = fmaxf(a3, 0.f);
}

__global__ void fc2_kernel(const float* __restrict__ w2, const float* __restrict__ b2) {
    int b0 = blockIdx.x * 4;
    int j = threadIdx.x; // 1024
    __shared__ float s_in[4][512];
    for (int idx = j; idx < 2048; idx += 1024) {
        int g = idx >> 9, k = idx & 511;
        s_in[g][k] = g_r1[(b0 + g) * 512 + k];
    }
    __syncthreads();
    float a0 = b2[j], a1 = a0, a2 = a0, a3 = a0;
#pragma unroll 4
    for (int k = 0; k < 512; k++) {
        float wv = w2[k * 1024 + j];
        a0 += s_in[0][k] * wv; a1 += s_in[1][k] * wv;
        a2 += s_in[2][k] * wv; a3 += s_in[3][k] * wv;
    }
    g_r2[(b0 + 0) * 1024 + j] = fmaxf(a0, 0.f);
    g_r2[(b0 + 1) * 1024 + j] = fmaxf(a1, 0.f);
    g_r2[(b0 + 2) * 1024 + j] = fmaxf(a2, 0.f);
    g_r2[(b0 + 3) * 1024 + j] = fmaxf(a3, 0.f);
}

__global__ void fc3_kernel(const float* __restrict__ w3, const float* __restrict__ b3,
                           float* __restrict__ recon) {
    int b0 = blockIdx.x * 4;
    int j = threadIdx.x; // 784
    __shared__ float s_in[4][1024];
    for (int idx = j; idx < 4096; idx += 784) {
        int g = idx >> 10, k = idx & 1023;
        s_in[g][k] = g_r2[(b0 + g) * 1024 + k];
    }
    __syncthreads();
    float a0 = b3[j], a1 = a0, a2 = a0, a3 = a0;
#pragma unroll 4
    for (int k = 0; k < 1024; k++) {
        float wv = w3[k * 784 + j];
        a0 += s_in[0][k] * wv; a1 += s_in[1][k] * wv;
        a2 += s_in[2][k] * wv; a3 += s_in[3][k] * wv;
    }
    recon[(b0 + 0) * 784 + j] = 1.f / (1.f + expf(-a0));
    recon[(b0 + 1) * 784 + j] = 1.f / (1.f + expf(-a1));
    recon[(b0 + 2) * 784 + j] = 1.f / (1.f + expf(-a2));
    recon[(b0 + 3) * 784 + j] = 1.f / (1.f + expf(-a3));
}

extern "C" void kernel_launch(void* const* d_in, const int* in_sizes, int n_in,
                              void* d_out, int out_size) {
    const float* x       = (const float*)d_in[0];
    const float* y       = (const float*)d_in[1];
    const float* conv1_w = (const float*)d_in[2];
    const float* conv1_b = (const float*)d_in[3];
    const float* prim_w  = (const float*)d_in[4];
    const float* prim_b  = (const float*)d_in[5];
    const float* digit_w = (const float*)d_in[6];
    const float* digit_b = (const float*)d_in[7];
    const float* w1      = (const float*)d_in[8];
    const float* b1      = (const float*)d_in[9];
    const float* w2      = (const float*)d_in[10];
    const float* b2      = (const float*)d_in[11];
    const float* w3      = (const float*)d_in[12];
    const float* b3      = (const float*)d_in[13];
    float* out = (float*)d_out;

    conv1_kernel<<<dim3(256, 256), 400>>>(x, conv1_w, conv1_b);
    pconv_kernel<<<dim3(4, 128), 144>>>(prim_w);
    squash_prim_kernel<<<(BB * IN_DIM + 255) / 256, 256>>>(prim_b);
    votes_kernel<<<dim3(IN_DIM, 8), 160>>>(digit_w);
    routing_kernel<<<BB, 640>>>(digit_b, out, 0, 0);
    routing_kernel<<<BB, 640>>>(digit_b, out, 1, 0);
    routing_kernel<<<BB, 640>>>(digit_b, out, 2, 1);
    fc1_kernel<<<64, 512>>>(y, w1, b1, out);
    fc2_kernel<<<64, 1024>>>(w2, b2);
    fc3_kernel<<<64, 784>>>(w3, b3, out + 40960);
}

// round 15
// speedup vs baseline: 1.2747x; 1.0878x over previous
#include <cuda_runtime.h>
#include <math.h>

#define BB 256
#define IN_DIM 1152

// packed f32x2 helpers (Blackwell sm_103a)
#define PACK_F32X2(out, lo, hi) \
    asm("mov.b64 %0, {%1, %2};" : "=l"(out) : "f"(lo), "f"(hi))
#define UNPACK_F32X2(lo, hi, in) \
    asm("mov.b64 {%0, %1}, %2;" : "=f"(lo), "=f"(hi) : "l"(in))
#define FFMA2(acc, a, b) \
    asm("fma.rn.f32x2 %0, %1, %2, %0;" : "+l"(acc) : "l"(a), "l"(b))

// ---- scratch (static device globals; no allocations anywhere) ----
__device__ float g_h[(size_t)BB * 256 * 400];         // conv1 out [B,256,20,20]
__device__ float g_pc2[2][(size_t)BB * 256 * 36];     // pconv partials (ic halves)
__device__ float g_x3[(size_t)BB * IN_DIM * 8];       // squashed+transposed [B,1152,8]
__device__ float g_votes[(size_t)BB * IN_DIM * 160];  // [B,1152,10,16]
__device__ float g_logits[(size_t)BB * IN_DIM * 10];  // [B,1152,10]
__device__ float g_r1[BB * 512];
__device__ float g_r2[BB * 1024];

// ---------------- conv1: [B,1,28,28] -> relu([B,256,20,20]) ----------------
__global__ void conv1_kernel(const float* __restrict__ x,
                             const float* __restrict__ w,
                             const float* __restrict__ bias) {
    int oc = blockIdx.x, b = blockIdx.y;
    int tid = threadIdx.x; // 400 threads = 20x20
    __shared__ float s_img[784];
    __shared__ float s_w[81];
    for (int idx = tid; idx < 784; idx += 400) s_img[idx] = x[b * 784 + idx];
    if (tid < 81) s_w[tid] = w[oc * 81 + tid];
    __syncthreads();
    int oy = tid / 20, ox = tid % 20;
    float acc = bias[oc];
#pragma unroll
    for (int kh = 0; kh < 9; kh++)
#pragma unroll
        for (int kw = 0; kw < 9; kw++)
            acc += s_img[(oy + kh) * 28 + ox + kw] * s_w[kh * 9 + kw];
    g_h[((size_t)(b * 256 + oc)) * 400 + tid] = fmaxf(acc, 0.f);
}

// ------- primary caps conv: [B,256,20,20] -> [B,256,6,6], k=9 s=2 -------
// block = (oc tile of 64, image pair, ic half); 144 threads;
// each thread: 2 images x 4 oc x 4 pos; 128-ic partial sum per block.
__global__ void pconv_kernel(const float* __restrict__ w) {
    int oc0 = blockIdx.x * 64;
    int b0 = blockIdx.y * 2;
    int half = blockIdx.z;
    int ic0 = half * 128;
    int tid = threadIdx.x; // 144
    int ocg = tid & 15;    // 16 groups of 4 oc
    int posg = tid >> 4;   // 9 groups of 4 positions
    __shared__ float2 s_h2[361];     // 19x19 patch, (img0,img1) interleaved
    __shared__ float s_w[64 * 81];   // 64 oc x 9x9, one ic (j-major)
    unsigned long long acc2[4][4];   // [oc][pos], lanes = (img0, img1)
#pragma unroll
    for (int j = 0; j < 4; j++)
#pragma unroll
        for (int p = 0; p < 4; p++) acc2[j][p] = 0ull;
    int off0[4];
#pragma unroll
    for (int p = 0; p < 4; p++) {
        int pos = posg * 4 + p;
        off0[p] = (pos / 6) * 2 * 19 + (pos % 6) * 2;
    }
    for (int ic = ic0; ic < ic0 + 128; ic++) {
        const float* hp0 = g_h + ((size_t)(b0 * 256 + ic)) * 400;
        const float* hp1 = g_h + ((size_t)((b0 + 1) * 256 + ic)) * 400;
        for (int idx = tid; idx < 361; idx += 144) {
            int src = (idx / 19) * 20 + idx % 19;
            float2 v;
            v.x = hp0[src];
            v.y = hp1[src];
            s_h2[idx] = v;
        }
        for (int idx = tid; idx < 64 * 81; idx += 144) {
            int j = idx / 81, k = idx - j * 81;
            s_w[idx] = w[((size_t)(oc0 + j) * 256 + ic) * 81 + k];
        }
        __syncthreads();
#pragma unroll
        for (int kh = 0; kh < 9; kh++) {
#pragma unroll
            for (int kw = 0; kw < 9; kw++) {
                unsigned long long hv2[4];
#pragma unroll
                for (int p = 0; p < 4; p++)
                    hv2[p] = *reinterpret_cast<const unsigned long long*>(
                        &s_h2[off0[p] + kh * 19 + kw]);
                unsigned long long wv2[4];
#pragma unroll
                for (int j = 0; j < 4; j++) {
                    float wv = s_w[(ocg * 4 + j) * 81 + kh * 9 + kw];
                    PACK_F32X2(wv2[j], wv, wv);
                }
#pragma unroll
                for (int j = 0; j < 4; j++)
#pragma unroll
                    for (int p = 0; p < 4; p++)
                        FFMA2(acc2[j][p], wv2[j], hv2[p]);
            }
        }
        __syncthreads();
    }
    float* pcout = g_pc2[half];
#pragma unroll
    for (int j = 0; j < 4; j++) {
        int oc = oc0 + ocg * 4 + j;
#pragma unroll
        for (int p = 0; p < 4; p++) {
            int pos = posg * 4 + p;
            float a0, a1;
            UNPACK_F32X2(a0, a1, acc2[j][p]);
            pcout[((size_t)(b0 * 256 + oc)) * 36 + pos] = a0;
            pcout[((size_t)((b0 + 1) * 256 + oc)) * 36 + pos] = a1;
        }
    }
}

// ---- primary squash + transpose -> x3 [B,1152,8] (sums the two ic halves) ----
__global__ void squash_prim_kernel(const float* __restrict__ prim_b) {
    int g = blockIdx.x * blockDim.x + threadIdx.x;
    if (g >= BB * IN_DIM) return;
    int i = g % IN_DIM;
    int b = g / IN_DIM;
    int cap = i / 36, pos = i % 36;
    float s[8];
    float n2 = 0.f;
#pragma unroll
    for (int a = 0; a < 8; a++) {
        size_t idx = ((size_t)(b * 256 + cap * 8 + a)) * 36 + pos;
        float v = (g_pc2[0][idx] + g_pc2[1][idx]) * (1.f / 32.f)
                  + prim_b[cap * 8 + a];
        s[a] = v;
        n2 += v * v;
    }
    float scale = (n2 / (1.f + n2)) * rsqrtf(n2 + 1e-9f);
#pragma unroll
    for (int a = 0; a < 8; a++) g_x3[(size_t)g * 8 + a] = s[a] * scale;
}

// ---- votes[b,i,o,t] = sum_a x3[b,i,a] * W[i,a,o,t] ----
// block = (i, tile of 32 b); W and x3 tile staged in smem.
__global__ void votes_kernel(const float* __restrict__ dw) {
    int i = blockIdx.x;
    int bt = blockIdx.y * 32;
    int t = threadIdx.x; // 160
    __shared__ float s_w[1280];
    __shared__ float s_x[32][8];
    for (int idx = t; idx < 1280; idx += 160) s_w[idx] = dw[(size_t)i * 1280 + idx];
    for (int idx = t; idx < 256; idx += 160) {
        int bb = idx >> 3, a = idx & 7;
        s_x[bb][a] = g_x3[((size_t)(bt + bb) * IN_DIM + i) * 8 + a];
    }
    __syncthreads();
    for (int bb = 0; bb < 32; bb++) {
        float acc = 0.f;
#pragma unroll
        for (int a = 0; a < 8; a++) acc += s_x[bb][a] * s_w[a * 160 + t];
        g_votes[((size_t)(bt + bb) * IN_DIM + i) * 160 + t] = acc;
    }
}

// ---- one full routing iteration per launch (640 threads, 4-way i-split) ----
__global__ void routing_kernel(const float* __restrict__ db,
                               float* __restrict__ out_digit,
                               int iter, int last) {
    int b = blockIdx.x;
    int tid = threadIdx.x; // 640
    __shared__ float s_route[IN_DIM * 10]; // 46080 B
    __shared__ float s_part[4 * 160];
    __shared__ float s_act[160];
    __shared__ float s_scale[10];
    const float* vbase = g_votes + (size_t)b * IN_DIM * 160;
    float* lbase = g_logits + (size_t)b * IN_DIM * 10;

    if (iter == 0) {
        for (int idx = tid; idx < IN_DIM * 10; idx += 640) s_route[idx] = 0.1f;
    } else {
        for (int i = tid; i < IN_DIM; i += 640) {
            float l[10];
            float m = -1e30f;
#pragma unroll
            for (int o = 0; o < 10; o++) { l[o] = lbase[i * 10 + o]; m = fmaxf(m, l[o]); }
            float s = 0.f;
#pragma unroll
            for (int o = 0; o < 10; o++) { l[o] = expf(l[o] - m); s += l[o]; }
            float inv = 1.f / s;
#pragma unroll
            for (int o = 0; o < 10; o++) s_route[i * 10 + o] = l[o] * inv;
        }
    }
    __syncthreads();

    // preact[b,o,t] = sum_i route * votes (i-range split 4 ways)
    {
        int g = tid / 160, ot = tid % 160, o = ot >> 4;
        float acc = 0.f;
        int i0 = g * 288, i1 = i0 + 288;
#pragma unroll 8
        for (int i = i0; i < i1; i++)
            acc += s_route[i * 10 + o] * vbase[(size_t)i * 160 + ot];
        s_part[g * 160 + ot] = acc;
    }
    __syncthreads();
    if (tid < 160)
        s_part[tid] = s_part[tid] + s_part[160 + tid] + s_part[320 + tid]
                      + s_part[480 + tid] + db[tid];
    __syncthreads();
    if (tid < 10) {
        float n2 = 0.f;
#pragma unroll
        for (int t = 0; t < 16; t++) { float v = s_part[tid * 16 + t]; n2 += v * v; }
        s_scale[tid] = (n2 / (1.f + n2)) * rsqrtf(n2 + 1e-9f);
    }
    __syncthreads();
    if (tid < 160) {
        float a = s_part[tid] * s_scale[tid >> 4];
        s_act[tid] = a;
        if (last) out_digit[b * 160 + tid] = a;
    }
    if (!last) {
        __syncthreads();
        for (int idx = tid; idx < IN_DIM * 10; idx += 640) {
            int i = idx / 10, o = idx - i * 10;
            const float* vp = vbase + (size_t)i * 160 + o * 16;
            float s = 0.f;
#pragma unroll
            for (int t = 0; t < 16; t++) s += vp[t] * s_act[o * 16 + t];
            if (iter == 0) lbase[idx] = s;
            else lbase[idx] += s;
        }
    }
}

// ---- reconstruction MLP (A-stationary in smem, coalesced weight reads, 4 batches/block) ----
__global__ void fc1_kernel(const float* __restrict__ yv, const float* __restrict__ w1,
                           const float* __restrict__ b1, const float* __restrict__ digit) {
    int b0 = blockIdx.x * 4;
    int j = threadIdx.x; // 512
    __shared__ float s_in[4][160];
    for (int idx = j; idx < 640; idx += 512) {
        int g = idx / 160, ot = idx - g * 160;
        s_in[g][ot] = digit[(b0 + g) * 160 + ot] * yv[(b0 + g) * 10 + (ot >> 4)];
    }
    __syncthreads();
    float a0 = b1[j], a1 = a0, a2 = a0, a3 = a0;
#pragma unroll 4
    for (int k = 0; k < 160; k++) {
        float wv = w1[k * 512 + j];
        a0 += s_in[0][k] * wv; a1 += s_in[1][k] * wv;
        a2 += s_in[2][k] * wv; a3 += s_in[3][k] * wv;
    }
    g_r1[(b0 + 0) * 512 + j] = fmaxf(a0, 0.f);
    g_r1[(b0 + 1) * 512 + j] = fmaxf(a1, 0.f);
    g_r1[(b0 + 2) * 512 + j] = fmaxf(a2, 0.f);
    g_r1[(b0 + 3) * 512 + j] = fmaxf(a3, 0.f);
}

__global__ void fc2_kernel(const float* __restrict__ w2, const float* __restrict__ b2) {
    int b0 = blockIdx.x * 4;
    int j = threadIdx.x; // 1024
    __shared__ float s_in[4][512];
    for (int idx = j; idx < 2048; idx += 1024) {
        int g = idx >> 9, k = idx & 511;
        s_in[g][k] = g_r1[(b0 + g) * 512 + k];
    }
    __syncthreads();
    float a0 = b2[j], a1 = a0, a2 = a0, a3 = a0;
#pragma unroll 4
    for (int k = 0; k < 512; k++) {
        float wv = w2[k * 1024 + j];
        a0 += s_in[0][k] * wv; a1 += s_in[1][k] * wv;
        a2 += s_in[2][k] * wv; a3 += s_in[3][k] * wv;
    }
    g_r2[(b0 + 0) * 1024 + j] = fmaxf(a0, 0.f);
    g_r2[(b0 + 1) * 1024 + j] = fmaxf(a1, 0.f);
    g_r2[(b0 + 2) * 1024 + j] = fmaxf(a2, 0.f);
    g_r2[(b0 + 3) * 1024 + j] = fmaxf(a3, 0.f);
}

__global__ void fc3_kernel(const float* __restrict__ w3, const float* __restrict__ b3,
                           float* __restrict__ recon) {
    int b0 = blockIdx.x * 4;
    int j = threadIdx.x; // 784
    __shared__ float s_in[4][1024];
    for (int idx = j; idx < 4096; idx += 784) {
        int g = idx >> 10, k = idx & 1023;
        s_in[g][k] = g_r2[(b0 + g) * 1024 + k];
    }
    __syncthreads();
    float a0 = b3[j], a1 = a0, a2 = a0, a3 = a0;
#pragma unroll 4
    for (int k = 0; k < 1024; k++) {
        float wv = w3[k * 784 + j];
        a0 += s_in[0][k] * wv; a1 += s_in[1][k] * wv;
        a2 += s_in[2][k] * wv; a3 += s_in[3][k] * wv;
    }
    recon[(b0 + 0) * 784 + j] = 1.f / (1.f + expf(-a0));
    recon[(b0 + 1) * 784 + j] = 1.f / (1.f + expf(-a1));
    recon[(b0 + 2) * 784 + j] = 1.f / (1.f + expf(-a2));
    recon[(b0 + 3) * 784 + j] = 1.f / (1.f + expf(-a3));
}

extern "C" void kernel_launch(void* const* d_in, const int* in_sizes, int n_in,
                              void* d_out, int out_size) {
    const float* x       = (const float*)d_in[0];
    const float* y       = (const float*)d_in[1];
    const float* conv1_w = (const float*)d_in[2];
    const float* conv1_b = (const float*)d_in[3];
    const float* prim_w  = (const float*)d_in[4];
    const float* prim_b  = (const float*)d_in[5];
    const float* digit_w = (const float*)d_in[6];
    const float* digit_b = (const float*)d_in[7];
    const float* w1      = (const float*)d_in[8];
    const float* b1      = (const float*)d_in[9];
    const float* w2      = (const float*)d_in[10];
    const float* b2      = (const float*)d_in[11];
    const float* w3      = (const float*)d_in[12];
    const float* b3      = (const float*)d_in[13];
    float* out = (float*)d_out;

    conv1_kernel<<<dim3(256, 256), 400>>>(x, conv1_w, conv1_b);
    pconv_kernel<<<dim3(4, 128, 2), 144>>>(prim_w);
    squash_prim_kernel<<<(BB * IN_DIM + 255) / 256, 256>>>(prim_b);
    votes_kernel<<<dim3(IN_DIM, 8), 160>>>(digit_w);
    routing_kernel<<<BB, 640>>>(digit_b, out, 0, 0);
    routing_kernel<<<BB, 640>>>(digit_b, out, 1, 0);
    routing_kernel<<<BB, 640>>>(digit_b, out, 2, 1);
    fc1_kernel<<<64, 512>>>(y, w1, b1, out);
    fc2_kernel<<<64, 1024>>>(w2, b2);
    fc3_kernel<<<64, 784>>>(w3, b3, out + 40960);
}